// round 5
// baseline (speedup 1.0000x reference)
#include <cuda_runtime.h>
#include <math.h>
#include <float.h>

#define NUM_CLASSES 200
#define NUM_PROTO   10
#define EMBED_D     512
#define NQ          8192
#define NBC         (NQ / 128)    // 64 big-chunks of 128 labels
#define ITERS       5
#define EPSF        0.01f
#define INV_EPS     100.0f
#define EPS_LOG     1e-8f
#define NCAP        192           // smem row capacity (mean n_c ~41, sd 6.4)
#define SROW        12            // padded S row stride (16B-aligned float4 reads)
#define FULLM       0xffffffffu

// ---------------- scratch (allocation-free: __device__ globals) ----------------
__device__ int   g_lab[NQ];       // labels converted to int32
// fallback scratch (only used if a class exceeds NCAP rows)
__device__ int   g_fidx[NQ];
__device__ float g_Sf[NQ * SROW];
__device__ float g_vf[NQ];
__device__ float g_if[NQ];

// ---------------- K1: detect label dtype, convert to int32 --------------------
__global__ void k_lab(const void* __restrict__ labels_raw) {
    __shared__ int s_is64;
    int tid = threadIdx.x;
    if (tid < 32) {
        // int64 interpretation of first 32 values all in [0,200) -> really int64
        long long v = ((const long long*)labels_raw)[tid];
        unsigned bal = __ballot_sync(FULLM, v >= 0 && v < NUM_CLASSES);
        if (tid == 0) s_is64 = (__popc(bal) >= 16) ? 1 : 0;
    }
    __syncthreads();
    int i = blockIdx.x * blockDim.x + tid;
    g_lab[i] = s_is64 ? (int)((const long long*)labels_raw)[i]
                      : ((const int*)labels_raw)[i];
}

__device__ __forceinline__ float dot4(float4 a, float4 b) {
    return a.x * b.x + a.y * b.y + a.z * b.z + a.w * b.w;
}
__device__ __forceinline__ float warp_sum(float v) {
    #pragma unroll
    for (int o = 16; o; o >>= 1) v += __shfl_xor_sync(FULLM, v, o);
    return v;
}
__device__ __forceinline__ float warp_max(float v) {
    #pragma unroll
    for (int o = 16; o; o >>= 1) v = fmaxf(v, __shfl_xor_sync(FULLM, v, o));
    return v;
}
// paired butterfly seed: after full butterfly, even lanes hold sum(a), odd sum(b)
__device__ __forceinline__ float pair_seed(float a, float b, int lane) {
    float x = (lane & 1) ? a : b;
    x = __shfl_xor_sync(FULLM, x, 1);
    return ((lane & 1) ? b : a) + x;
}

// ---------------- fused per-class body (state in smem or global fallback) ------
template<bool SM>
__device__ __forceinline__ void class_body(
    int c, int n_c,
    const float* __restrict__ tokens,
    float* __restrict__ out,
    const float* sp, const int* IDX,
    float* S, float* V, float* IV,
    float* su, float* red, float* sinv)
{
    int tid = threadIdx.x;
    int wid = tid >> 5, lane = tid & 31;

    for (int i = tid; i < n_c; i += 512) V[i] = 0.0f;
    __syncthreads();

    // --- phase A: per-row norm + 10 masked dots (warp per row, paired reduce) ---
    for (int i = wid; i < n_c; i += 16) {
        int n = IDX[i];
        const float4* tp = (const float4*)(tokens + (size_t)n * EMBED_D);
        float4 t0 = tp[lane], t1 = tp[lane + 32], t2 = tp[lane + 64], t3 = tp[lane + 96];
        float d[11];
        d[10] = dot4(t0, t0) + dot4(t1, t1) + dot4(t2, t2) + dot4(t3, t3);  // ss
        #pragma unroll
        for (int j = 0; j < NUM_PROTO; j++) {
            const float4* pp = (const float4*)(sp + j * EMBED_D);
            d[j] = dot4(t0, pp[lane]) + dot4(t1, pp[lane + 32]) +
                   dot4(t2, pp[lane + 64]) + dot4(t3, pp[lane + 96]);
        }
        float cr[6];
        cr[0] = pair_seed(d[10], d[0], lane);
        cr[1] = pair_seed(d[1],  d[2], lane);
        cr[2] = pair_seed(d[3],  d[4], lane);
        cr[3] = pair_seed(d[5],  d[6], lane);
        cr[4] = pair_seed(d[7],  d[8], lane);
        cr[5] = pair_seed(d[9],  d[9], lane);
        #pragma unroll
        for (int o = 2; o < 32; o <<= 1) {
            #pragma unroll
            for (int p = 0; p < 6; p++) cr[p] += __shfl_xor_sync(FULLM, cr[p], o);
        }
        float inv = rsqrtf(__shfl_sync(FULLM, cr[0], 0));   // ss on lane 0
        if (lane == 0) {
            IV[i] = inv;
            S[i * SROW + 1] = cr[1] * inv; S[i * SROW + 3] = cr[2] * inv;
            S[i * SROW + 5] = cr[3] * inv; S[i * SROW + 7] = cr[4] * inv;
            S[i * SROW + 9] = cr[5] * inv;
        } else if (lane == 1) {
            S[i * SROW + 0] = cr[0] * inv; S[i * SROW + 2] = cr[1] * inv;
            S[i * SROW + 4] = cr[2] * inv; S[i * SROW + 6] = cr[3] * inv;
            S[i * SROW + 8] = cr[4] * inv;
        }
    }
    __syncthreads();

    // --- phase B: 5 Sinkhorn iterations ---
    const float log_a = __logf(1.0f / (float)NUM_PROTO + EPS_LOG);
    const float log_b = __logf(1.0f / (float)n_c + EPS_LOG);
    for (int it = 0; it < ITERS; it++) {
        if (wid < NUM_PROTO) {       // u: warp j, two-pass max->sum LSE
            int j = wid;
            float m = -FLT_MAX;
            for (int i = lane; i < n_c; i += 32)
                m = fmaxf(m, S[i * SROW + j] + V[i]);
            m = warp_max(m);
            float s = 0.0f;
            for (int i = lane; i < n_c; i += 32)
                s += __expf((S[i * SROW + j] + V[i] - m) * INV_EPS);
            s = warp_sum(s);
            if (lane == 0) su[j] = EPSF * log_a - m - EPSF * __logf(s);
        }
        __syncthreads();
        for (int i = tid; i < n_c; i += 512) {   // v: thread per row
            const float4 s0 = *(const float4*)(S + i * SROW);
            const float4 s1 = *(const float4*)(S + i * SROW + 4);
            const float4 s2 = *(const float4*)(S + i * SROW + 8);
            float b[NUM_PROTO] = {
                s0.x + su[0], s0.y + su[1], s0.z + su[2], s0.w + su[3],
                s1.x + su[4], s1.y + su[5], s1.z + su[6], s1.w + su[7],
                s2.x + su[8], s2.y + su[9] };
            float m = b[0];
            #pragma unroll
            for (int j = 1; j < NUM_PROTO; j++) m = fmaxf(m, b[j]);
            float s = 0.0f;
            #pragma unroll
            for (int j = 0; j < NUM_PROTO; j++) s += __expf((b[j] - m) * INV_EPS);
            V[i] = EPSF * log_b - m - EPSF * __logf(s);
        }
        __syncthreads();
    }

    // --- phase C: column-normalized transport weights * inv-norm, in place ---
    for (int i = tid; i < n_c; i += 512) {
        float vv = V[i];
        const float4 s0 = *(const float4*)(S + i * SROW);
        const float4 s1 = *(const float4*)(S + i * SROW + 4);
        const float4 s2 = *(const float4*)(S + i * SROW + 8);
        float w[NUM_PROTO] = {
            __expf((s0.x + su[0] + vv) * INV_EPS), __expf((s0.y + su[1] + vv) * INV_EPS),
            __expf((s0.z + su[2] + vv) * INV_EPS), __expf((s0.w + su[3] + vv) * INV_EPS),
            __expf((s1.x + su[4] + vv) * INV_EPS), __expf((s1.y + su[5] + vv) * INV_EPS),
            __expf((s1.z + su[6] + vv) * INV_EPS), __expf((s1.w + su[7] + vv) * INV_EPS),
            __expf((s2.x + su[8] + vv) * INV_EPS), __expf((s2.y + su[9] + vv) * INV_EPS) };
        float cs = 0.0f;
        #pragma unroll
        for (int j = 0; j < NUM_PROTO; j++) cs += w[j];
        float sc = IV[i] / cs;       // fold 1/||tok|| so phase D uses raw tokens
        *(float4*)(S + i * SROW)     = make_float4(w[0]*sc, w[1]*sc, w[2]*sc, w[3]*sc);
        *(float4*)(S + i * SROW + 4) = make_float4(w[4]*sc, w[5]*sc, w[6]*sc, w[7]*sc);
        *(float4*)(S + i * SROW + 8) = make_float4(w[8]*sc, w[9]*sc, 0.0f, 0.0f);
    }
    __syncthreads();

    // --- phase D: new_protos = weights^T @ raw_tokens (thread owns dim d) ---
    int d = tid;
    const float* tb = tokens + d;
    float acc[NUM_PROTO];
    #pragma unroll
    for (int j = 0; j < NUM_PROTO; j++) acc[j] = 0.0f;
    int i = 0;
    for (; i + 2 <= n_c; i += 2) {
        float ta = __ldg(tb + (size_t)IDX[i]     * EMBED_D);   // L1-warm from phase A
        float tc = __ldg(tb + (size_t)IDX[i + 1] * EMBED_D);
        const float4 p0 = *(const float4*)(S + i * SROW);
        const float4 p1 = *(const float4*)(S + i * SROW + 4);
        const float4 p2 = *(const float4*)(S + i * SROW + 8);
        const float4 q0 = *(const float4*)(S + (i + 1) * SROW);
        const float4 q1 = *(const float4*)(S + (i + 1) * SROW + 4);
        const float4 q2 = *(const float4*)(S + (i + 1) * SROW + 8);
        acc[0] += p0.x * ta; acc[1] += p0.y * ta; acc[2] += p0.z * ta; acc[3] += p0.w * ta;
        acc[4] += p1.x * ta; acc[5] += p1.y * ta; acc[6] += p1.z * ta; acc[7] += p1.w * ta;
        acc[8] += p2.x * ta; acc[9] += p2.y * ta;
        acc[0] += q0.x * tc; acc[1] += q0.y * tc; acc[2] += q0.z * tc; acc[3] += q0.w * tc;
        acc[4] += q1.x * tc; acc[5] += q1.y * tc; acc[6] += q1.z * tc; acc[7] += q1.w * tc;
        acc[8] += q2.x * tc; acc[9] += q2.y * tc;
    }
    if (i < n_c) {
        float ta = __ldg(tb + (size_t)IDX[i] * EMBED_D);
        const float4 p0 = *(const float4*)(S + i * SROW);
        const float4 p1 = *(const float4*)(S + i * SROW + 4);
        const float4 p2 = *(const float4*)(S + i * SROW + 8);
        acc[0] += p0.x * ta; acc[1] += p0.y * ta; acc[2] += p0.z * ta; acc[3] += p0.w * ta;
        acc[4] += p1.x * ta; acc[5] += p1.y * ta; acc[6] += p1.z * ta; acc[7] += p1.w * ta;
        acc[8] += p2.x * ta; acc[9] += p2.y * ta;
    }

    // --- phase E: momentum blend + paired l2-norm reductions + writeout ---
    float r[NUM_PROTO];
    #pragma unroll
    for (int j = 0; j < NUM_PROTO; j++)
        r[j] = 0.98f * sp[j * EMBED_D + d] + 0.02f * acc[j];
    float cr[5];
    #pragma unroll
    for (int p = 0; p < 5; p++)
        cr[p] = pair_seed(r[2*p] * r[2*p], r[2*p+1] * r[2*p+1], lane);
    #pragma unroll
    for (int o = 2; o < 32; o <<= 1) {
        #pragma unroll
        for (int p = 0; p < 5; p++) cr[p] += __shfl_xor_sync(FULLM, cr[p], o);
    }
    if (lane < 2) {
        #pragma unroll
        for (int p = 0; p < 5; p++) red[wid * NUM_PROTO + 2*p + lane] = cr[p];
    }
    __syncthreads();
    if (wid < NUM_PROTO) {
        int j = wid;
        float y = (lane < 16) ? red[lane * NUM_PROTO + j] : 0.0f;
        y = warp_sum(y);
        if (lane == 0) sinv[j] = rsqrtf(y);
    }
    __syncthreads();
    #pragma unroll
    for (int j = 0; j < NUM_PROTO; j++)
        out[(size_t)(c * NUM_PROTO + j) * EMBED_D + d] = r[j] * sinv[j];
}

// ---------------- K2: fused per-class kernel -----------------------------------
__global__ void __launch_bounds__(512, 2) k_main(const float* __restrict__ tokens,
                                                 const float* __restrict__ protos,
                                                 float* __restrict__ out) {
    __shared__ __align__(16) float sp[NUM_PROTO * EMBED_D];   // 20 KB
    __shared__ __align__(16) float ssS[NCAP * SROW];          // 9 KB
    __shared__ float ssV[NCAP];
    __shared__ float ssI[NCAP];
    __shared__ int   sidx[NCAP];
    __shared__ int   ccnt[NBC];                               // 64 big-chunk counts
    __shared__ float su[NUM_PROTO];
    __shared__ float red[16 * NUM_PROTO];
    __shared__ float sinv[NUM_PROTO];
    __shared__ int   s_n, s_lt;

    int c    = blockIdx.x;
    int tid  = threadIdx.x;
    int wid  = tid >> 5, lane = tid & 31;

    // stage prototypes early (DRAM loads in flight during label scan)
    {
        const float4* pg = (const float4*)(protos + (size_t)c * NUM_PROTO * EMBED_D);
        float4* ps = (float4*)sp;
        for (int i = tid; i < NUM_PROTO * EMBED_D / 4; i += 512) ps[i] = pg[i];
    }
    if (tid == 0) s_lt = 0;
    __syncthreads();

    const int4* lab4 = (const int4*)g_lab;

    // --- pass 1: 4 big-chunks per warp; each int4 load = 128 labels/warp ---
    int lt_local = 0;
    #pragma unroll
    for (int k = 0; k < NBC / 16; k++) {
        int bc = wid * (NBC / 16) + k;
        int4 v = lab4[bc * 32 + lane];            // unconditional -> batched MLP
        unsigned b0 = __ballot_sync(FULLM, v.x == c);
        unsigned b1 = __ballot_sync(FULLM, v.y == c);
        unsigned b2 = __ballot_sync(FULLM, v.z == c);
        unsigned b3 = __ballot_sync(FULLM, v.w == c);
        unsigned l0 = __ballot_sync(FULLM, v.x < c);
        unsigned l1 = __ballot_sync(FULLM, v.y < c);
        unsigned l2 = __ballot_sync(FULLM, v.z < c);
        unsigned l3 = __ballot_sync(FULLM, v.w < c);
        if (lane == 0) {
            ccnt[bc] = __popc(b0) + __popc(b1) + __popc(b2) + __popc(b3);
            lt_local += __popc(l0) + __popc(l1) + __popc(l2) + __popc(l3);
        }
    }
    if (lane == 0 && lt_local) atomicAdd(&s_lt, lt_local);   // int: deterministic
    __syncthreads();

    // --- exclusive scan over 64 counts (warp 0, two groups with carry) ---
    if (wid == 0) {
        int base = 0;
        #pragma unroll
        for (int g = 0; g < NBC / 32; g++) {
            int v = ccnt[g * 32 + lane];
            int inc = v;
            #pragma unroll
            for (int o = 1; o < 32; o <<= 1) {
                int t = __shfl_up_sync(FULLM, inc, o);
                if (lane >= o) inc += t;
            }
            ccnt[g * 32 + lane] = base + inc - v;            // exclusive
            base += __shfl_sync(FULLM, inc, 31);
        }
        if (lane == 0) s_n = base;
    }
    __syncthreads();

    int n_c = s_n;
    if (n_c == 0) {   // out = l2norm(0.98*proto) = proto (unit-norm input)
        #pragma unroll
        for (int j = 0; j < NUM_PROTO; j++)
            out[(size_t)(c * NUM_PROTO + j) * EMBED_D + tid] = sp[j * EMBED_D + tid];
        return;
    }
    bool sm  = (n_c <= NCAP);
    int  off = s_lt;

    // --- pass 2: ballot-rank compaction, order-preserving (loads L1-hot) ---
    #pragma unroll
    for (int k = 0; k < NBC / 16; k++) {
        int bc = wid * (NBC / 16) + k;
        int4 v = lab4[bc * 32 + lane];
        int n0 = bc * 128 + lane * 4;
        unsigned b0 = __ballot_sync(FULLM, v.x == c);
        unsigned b1 = __ballot_sync(FULLM, v.y == c);
        unsigned b2 = __ballot_sync(FULLM, v.z == c);
        unsigned b3 = __ballot_sync(FULLM, v.w == c);
        unsigned lt = (1u << lane) - 1u;
        int base = ccnt[bc];
        int c0 = __popc(b0), c1 = __popc(b1), c2 = __popc(b2);
        if (v.x == c) { int p = base + __popc(b0 & lt);
                        if (sm) sidx[p] = n0;     else g_fidx[off + p] = n0; }
        if (v.y == c) { int p = base + c0 + __popc(b1 & lt);
                        if (sm) sidx[p] = n0 + 1; else g_fidx[off + p] = n0 + 1; }
        if (v.z == c) { int p = base + c0 + c1 + __popc(b2 & lt);
                        if (sm) sidx[p] = n0 + 2; else g_fidx[off + p] = n0 + 2; }
        if (v.w == c) { int p = base + c0 + c1 + c2 + __popc(b3 & lt);
                        if (sm) sidx[p] = n0 + 3; else g_fidx[off + p] = n0 + 3; }
    }
    __syncthreads();

    if (sm) {
        class_body<true >(c, n_c, tokens, out, sp, sidx,
                          ssS, ssV, ssI, su, red, sinv);
    } else {  // statistically unreachable; correct fallback via global scratch
        class_body<false>(c, n_c, tokens, out, sp, g_fidx + off,
                          g_Sf + (size_t)off * SROW, g_vf + off, g_if + off,
                          su, red, sinv);
    }
}

// -------------------------------- launch ---------------------------------------
extern "C" void kernel_launch(void* const* d_in, const int* in_sizes, int n_in,
                              void* d_out, int out_size) {
    const float* tokens = (const float*)d_in[0];
    const void*  labels = d_in[1];
    const float* protos = (const float*)d_in[2];
    float* out = (float*)d_out;

    k_lab<<<NQ / 1024, 1024>>>(labels);
    k_main<<<NUM_CLASSES, 512>>>(tokens, protos, out);
}

// round 7
// speedup vs baseline: 1.3541x; 1.3541x over previous
#include <cuda_runtime.h>
#include <math.h>
#include <float.h>

#define NUM_CLASSES 200
#define NUM_PROTO   10
#define EMBED_D     512
#define NQ          8192
#define NBC         (NQ / 128)    // 64 big-chunks of 128 labels
#define ITERS       5
#define EPSF        0.01f
#define INV_EPS     100.0f
#define EPS_LOG     1e-8f
#define NCAP        192           // smem row capacity (mean n_c ~41, sd 6.4)
#define FULLM       0xffffffffu

// ---------------- scratch (allocation-free: __device__ globals) ----------------
__device__ int   g_lab[NQ];       // labels converted to int32
// fallback scratch (only used if a class exceeds NCAP rows)
__device__ int   g_fidx[NQ];
__device__ float g_Sf[NQ * NUM_PROTO];
__device__ float g_vf[NQ];
__device__ float g_if[NQ];

// ---------------- K1: detect label dtype, convert to int32 --------------------
__global__ void k_lab(const void* __restrict__ labels_raw) {
    __shared__ int s_is64;
    int tid = threadIdx.x;
    if (tid < 32) {
        // int64 interpretation of first 32 values all in [0,200) -> really int64
        long long v = ((const long long*)labels_raw)[tid];
        unsigned bal = __ballot_sync(FULLM, v >= 0 && v < NUM_CLASSES);
        if (tid == 0) s_is64 = (__popc(bal) >= 16) ? 1 : 0;
    }
    __syncthreads();
    int i = blockIdx.x * blockDim.x + tid;
    g_lab[i] = s_is64 ? (int)((const long long*)labels_raw)[i]
                      : ((const int*)labels_raw)[i];
}

__device__ __forceinline__ float dot4(float4 a, float4 b) {
    return a.x * b.x + a.y * b.y + a.z * b.z + a.w * b.w;
}
__device__ __forceinline__ float warp_sum(float v) {
    #pragma unroll
    for (int o = 16; o; o >>= 1) v += __shfl_xor_sync(FULLM, v, o);
    return v;
}
__device__ __forceinline__ float warp_max(float v) {
    #pragma unroll
    for (int o = 16; o; o >>= 1) v = fmaxf(v, __shfl_xor_sync(FULLM, v, o));
    return v;
}

// ---------------- fused per-class body (round-3 structure, fast-math) ----------
template<bool SM>
__device__ __forceinline__ void class_body(
    int c, int n_c,
    const float* __restrict__ tokens,
    float* __restrict__ out,
    const float* sp, const int* IDX,
    float* S, float* V, float* IV,
    float* su, float* red, float* sinv)
{
    int tid = threadIdx.x;
    int wid = tid >> 5, lane = tid & 31;

    for (int i = tid; i < n_c; i += 512) V[i] = 0.0f;
    __syncthreads();

    // --- phase A: per-row norm + 10 masked dots (warp per row, reduce per-j) ---
    for (int i = wid; i < n_c; i += 16) {
        int n = IDX[i];
        const float4* tp = (const float4*)(tokens + (size_t)n * EMBED_D);
        float4 t0 = tp[lane], t1 = tp[lane + 32], t2 = tp[lane + 64], t3 = tp[lane + 96];
        float ss = dot4(t0, t0) + dot4(t1, t1) + dot4(t2, t2) + dot4(t3, t3);
        ss = warp_sum(ss);
        float inv = rsqrtf(ss);
        if (lane == 0) IV[i] = inv;
        #pragma unroll
        for (int j = 0; j < NUM_PROTO; j++) {
            const float4* pp = (const float4*)(sp + j * EMBED_D);
            float d = dot4(t0, pp[lane]) + dot4(t1, pp[lane + 32]) +
                      dot4(t2, pp[lane + 64]) + dot4(t3, pp[lane + 96]);
            d = warp_sum(d);
            if (lane == 0) S[i * NUM_PROTO + j] = d * inv;
        }
    }
    __syncthreads();

    // --- phase B: 5 Sinkhorn iterations ---
    const float log_a = __logf(1.0f / (float)NUM_PROTO + EPS_LOG);
    const float log_b = __logf(1.0f / (float)n_c + EPS_LOG);
    for (int it = 0; it < ITERS; it++) {
        if (wid < NUM_PROTO) {       // u: warp j, two-pass max -> sum LSE
            int j = wid;
            float m = -FLT_MAX;
            for (int i = lane; i < n_c; i += 32)
                m = fmaxf(m, S[i * NUM_PROTO + j] + V[i]);
            m = warp_max(m);
            float s = 0.0f;
            for (int i = lane; i < n_c; i += 32)
                s += __expf((S[i * NUM_PROTO + j] + V[i] - m) * INV_EPS);
            s = warp_sum(s);
            if (lane == 0) su[j] = EPSF * log_a - m - EPSF * __logf(s);
        }
        __syncthreads();
        for (int i = tid; i < n_c; i += 512) {   // v: thread per row
            float b[NUM_PROTO];
            float m = -FLT_MAX;
            #pragma unroll
            for (int j = 0; j < NUM_PROTO; j++) {
                b[j] = S[i * NUM_PROTO + j] + su[j];
                m = fmaxf(m, b[j]);
            }
            float s = 0.0f;
            #pragma unroll
            for (int j = 0; j < NUM_PROTO; j++) s += __expf((b[j] - m) * INV_EPS);
            V[i] = EPSF * log_b - m - EPSF * __logf(s);
        }
        __syncthreads();
    }

    // --- phase C: column-normalized transport weights * inv-norm, in place ---
    for (int i = tid; i < n_c; i += 512) {
        float vv = V[i];
        float w[NUM_PROTO];
        float cs = 0.0f;
        #pragma unroll
        for (int j = 0; j < NUM_PROTO; j++) {
            w[j] = __expf((S[i * NUM_PROTO + j] + su[j] + vv) * INV_EPS);
            cs += w[j];
        }
        float sc = IV[i] / cs;       // fold 1/||tok|| so phase D uses raw tokens
        #pragma unroll
        for (int j = 0; j < NUM_PROTO; j++) S[i * NUM_PROTO + j] = w[j] * sc;
    }
    __syncthreads();

    // --- phase D: new_protos = weights^T @ raw_tokens (thread owns dim d) ---
    int d = tid;
    float acc[NUM_PROTO];
    #pragma unroll
    for (int j = 0; j < NUM_PROTO; j++) acc[j] = 0.0f;
    #pragma unroll 4
    for (int i = 0; i < n_c; i++) {
        float t = __ldg(tokens + (size_t)IDX[i] * EMBED_D + d);  // L1-warm (phase A)
        #pragma unroll
        for (int j = 0; j < NUM_PROTO; j++) acc[j] += S[i * NUM_PROTO + j] * t;
    }

    // --- phase E: momentum blend + batched per-row l2norm + writeout ---
    float r[NUM_PROTO];
    #pragma unroll
    for (int j = 0; j < NUM_PROTO; j++) {
        r[j] = 0.98f * sp[j * EMBED_D + d] + 0.02f * acc[j];
        float x = warp_sum(r[j] * r[j]);
        if (lane == 0) red[wid * NUM_PROTO + j] = x;
    }
    __syncthreads();
    if (wid < NUM_PROTO) {
        int j = wid;
        float y = (lane < 16) ? red[lane * NUM_PROTO + j] : 0.0f;
        y = warp_sum(y);
        if (lane == 0) sinv[j] = rsqrtf(y);
    }
    __syncthreads();
    #pragma unroll
    for (int j = 0; j < NUM_PROTO; j++)
        out[(size_t)(c * NUM_PROTO + j) * EMBED_D + d] = r[j] * sinv[j];
}

// ---------------- K2: fused per-class kernel -----------------------------------
__global__ void __launch_bounds__(512) k_main(const float* __restrict__ tokens,
                                              const float* __restrict__ protos,
                                              float* __restrict__ out) {
    __shared__ __align__(16) float sp[NUM_PROTO * EMBED_D];   // 20 KB
    __shared__ float ssS[NCAP * NUM_PROTO];                   // 7.5 KB
    __shared__ float ssV[NCAP];
    __shared__ float ssI[NCAP];
    __shared__ int   sidx[NCAP];
    __shared__ int   ccnt[NBC];                               // 64 big-chunk counts
    __shared__ float su[NUM_PROTO];
    __shared__ float red[16 * NUM_PROTO];
    __shared__ float sinv[NUM_PROTO];
    __shared__ int   s_n, s_lt;

    int c    = blockIdx.x;
    int tid  = threadIdx.x;
    int wid  = tid >> 5, lane = tid & 31;

    // stage prototypes early (DRAM loads in flight during label scan)
    {
        const float4* pg = (const float4*)(protos + (size_t)c * NUM_PROTO * EMBED_D);
        float4* ps = (float4*)sp;
        for (int i = tid; i < NUM_PROTO * EMBED_D / 4; i += 512) ps[i] = pg[i];
    }
    if (tid == 0) s_lt = 0;
    __syncthreads();

    const int4* lab4 = (const int4*)g_lab;

    // --- pass 1: 4 big-chunks per warp; each int4 load = 128 labels/warp ---
    int lt_local = 0;
    #pragma unroll
    for (int k = 0; k < NBC / 16; k++) {
        int bc = wid * (NBC / 16) + k;
        int4 v = lab4[bc * 32 + lane];
        unsigned b0 = __ballot_sync(FULLM, v.x == c);
        unsigned b1 = __ballot_sync(FULLM, v.y == c);
        unsigned b2 = __ballot_sync(FULLM, v.z == c);
        unsigned b3 = __ballot_sync(FULLM, v.w == c);
        unsigned l0 = __ballot_sync(FULLM, v.x < c);
        unsigned l1 = __ballot_sync(FULLM, v.y < c);
        unsigned l2 = __ballot_sync(FULLM, v.z < c);
        unsigned l3 = __ballot_sync(FULLM, v.w < c);
        if (lane == 0) {
            ccnt[bc] = __popc(b0) + __popc(b1) + __popc(b2) + __popc(b3);
            lt_local += __popc(l0) + __popc(l1) + __popc(l2) + __popc(l3);
        }
    }
    if (lane == 0 && lt_local) atomicAdd(&s_lt, lt_local);   // int: deterministic
    __syncthreads();

    // --- exclusive scan over 64 counts (warp 0, two groups with carry) ---
    if (wid == 0) {
        int base = 0;
        #pragma unroll
        for (int g = 0; g < NBC / 32; g++) {
            int v = ccnt[g * 32 + lane];
            int inc = v;
            #pragma unroll
            for (int o = 1; o < 32; o <<= 1) {
                int t = __shfl_up_sync(FULLM, inc, o);
                if (lane >= o) inc += t;
            }
            ccnt[g * 32 + lane] = base + inc - v;            // exclusive
            base += __shfl_sync(FULLM, inc, 31);
        }
        if (lane == 0) s_n = base;
    }
    __syncthreads();

    int n_c = s_n;
    if (n_c == 0) {   // out = l2norm(0.98*proto) = proto (unit-norm input)
        #pragma unroll
        for (int j = 0; j < NUM_PROTO; j++)
            out[(size_t)(c * NUM_PROTO + j) * EMBED_D + tid] = sp[j * EMBED_D + tid];
        return;
    }
    bool sm  = (n_c <= NCAP);
    int  off = s_lt;

    // --- pass 2: ballot-rank compaction, order-preserving (loads L1-hot) ---
    #pragma unroll
    for (int k = 0; k < NBC / 16; k++) {
        int bc = wid * (NBC / 16) + k;
        int4 v = lab4[bc * 32 + lane];
        int n0 = bc * 128 + lane * 4;
        unsigned b0 = __ballot_sync(FULLM, v.x == c);
        unsigned b1 = __ballot_sync(FULLM, v.y == c);
        unsigned b2 = __ballot_sync(FULLM, v.z == c);
        unsigned b3 = __ballot_sync(FULLM, v.w == c);
        unsigned lt = (1u << lane) - 1u;
        int base = ccnt[bc];
        int c0 = __popc(b0), c1 = __popc(b1), c2 = __popc(b2);
        if (v.x == c) { int p = base + __popc(b0 & lt);
                        if (sm) sidx[p] = n0;     else g_fidx[off + p] = n0; }
        if (v.y == c) { int p = base + c0 + __popc(b1 & lt);
                        if (sm) sidx[p] = n0 + 1; else g_fidx[off + p] = n0 + 1; }
        if (v.z == c) { int p = base + c0 + c1 + __popc(b2 & lt);
                        if (sm) sidx[p] = n0 + 2; else g_fidx[off + p] = n0 + 2; }
        if (v.w == c) { int p = base + c0 + c1 + c2 + __popc(b3 & lt);
                        if (sm) sidx[p] = n0 + 3; else g_fidx[off + p] = n0 + 3; }
    }
    __syncthreads();

    if (sm) {
        class_body<true >(c, n_c, tokens, out, sp, sidx,
                          ssS, ssV, ssI, su, red, sinv);
    } else {  // statistically unreachable; correct fallback via global scratch
        class_body<false>(c, n_c, tokens, out, sp, g_fidx + off,
                          g_Sf + (size_t)off * NUM_PROTO, g_vf + off, g_if + off,
                          su, red, sinv);
    }
}

// -------------------------------- launch ---------------------------------------
extern "C" void kernel_launch(void* const* d_in, const int* in_sizes, int n_in,
                              void* d_out, int out_size) {
    const float* tokens = (const float*)d_in[0];
    const void*  labels = d_in[1];
    const float* protos = (const float*)d_in[2];
    float* out = (float*)d_out;

    k_lab<<<NQ / 1024, 1024>>>(labels);
    k_main<<<NUM_CLASSES, 512>>>(tokens, protos, out);
}